// round 6
// baseline (speedup 1.0000x reference)
#include <cuda_runtime.h>
#include <cstdint>

// Problem constants
#define BB    128
#define LL    9
#define KK    3
#define CIN   256
#define COUT  256
#define PP    1680
#define NSUB  84          // C(9,3)
#define OCH   8           // float4 per channel-eighth (32 floats)
#define NOQ   8           // channel eighths

// Scratch
__device__ int g_sids[PP];   // packed subset ranks per permutation

// Packed fp32x2 FMA (Blackwell FFMA2)
__device__ __forceinline__ void ffma2(unsigned long long& d,
                                      unsigned long long a,
                                      unsigned long long b) {
    asm("fma.rn.f32x2 %0, %1, %2, %0;" : "+l"(d) : "l"(a), "l"(b));
}

// ---------------------------------------------------------------------------
// Kernel A: per-permutation subset ranks from binary mask M (simple R1 form —
// latency-bound, ~4us; the smem-staged variant was slower).
// rank = l1 + C(l2,2) + C(l3,3)  (colex), 3 ranks packed 10 bits each.
// ---------------------------------------------------------------------------
__global__ void sid_kernel(const float* __restrict__ M) {
    int p = blockIdx.x * blockDim.x + threadIdx.x;
    if (p >= PP) return;
    int packed = 0;
#pragma unroll
    for (int a = 0; a < KK; a++) {
        int mask = 0;
#pragma unroll
        for (int l = 0; l < LL; l++)
            if (M[(a * PP + p) * LL + l] > 0.5f) mask |= (1 << l);
        int m  = mask;
        int l1 = __ffs(m) - 1; m &= m - 1;
        int l2 = __ffs(m) - 1; m &= m - 1;
        int l3 = __ffs(m) - 1;
        int rank = l1 + (l2 * (l2 - 1)) / 2 + (l3 * (l3 - 1) * (l3 - 2)) / 6;
        packed |= rank << (a * 10);
    }
    g_sids[p] = packed;
}

// ---------------------------------------------------------------------------
// Fused kernel: per block (b, oq) with oq = channel-eighth (32 channels).
//  Phase 1: load x[b] (9 KB) + all 1680 packed sids into smem.
//  Phase 2: compute Z slice Z[l,a,o] = x[b,l,:]*W[a,og,:] — 96 (a,o) columns
//           x 4 c-splits = 384 threads; W-slice streamed from L2; butterfly
//           shfl reduce over the 4 c-splits.
//  Phase 3: build T_a[sid][o] = sum_{l in subset sid} Z[l,a,o] (252 x 8 float4),
//           subset decoded per-thread by colex unranking (no serial mask loop).
//  Phase 4: gather y[b,p,og] = T0[s0]+T1[s1]+T2[s2]; streaming STG.128.
// smem = 50.4 KB -> 3-4 blocks/SM; grid 1024 -> phases of co-resident blocks
// overlap so the DRAM store stream stays busy.
// ---------------------------------------------------------------------------
#define NT 384
#define SM_TT  (KK * NSUB * OCH * 16)      // 32256
#define SM_XS  (LL * 64 * 16)              // 9216
#define SM_ZS  (27 * 32 * 4)               // 3456
#define SM_PS  (PP * 4)                    // 6720
#define SM_ALL (SM_TT + SM_XS + SM_ZS + SM_PS)   // 51648

__global__ void __launch_bounds__(NT, 3)
y_fused(const float* __restrict__ x, const float* __restrict__ W,
        float4* __restrict__ out) {
    extern __shared__ char smem[];
    float4* Tt   = reinterpret_cast<float4*>(smem);
    float4* xs4  = reinterpret_cast<float4*>(smem + SM_TT);
    float*  Zs   = reinterpret_cast<float*>(smem + SM_TT + SM_XS);
    float4* Zs4  = reinterpret_cast<float4*>(Zs);
    int*    psid = reinterpret_cast<int*>(smem + SM_TT + SM_XS + SM_ZS);

    const int tid = threadIdx.x;
    const int b   = blockIdx.x;
    const int oq  = blockIdx.y;          // 0..7

    // ---- Phase 1: stage x[b] and sids -----------------------------------
    const float4* xg = reinterpret_cast<const float4*>(x + (size_t)b * LL * CIN);
    for (int i = tid; i < LL * 64; i += NT) xs4[i] = xg[i];
    for (int i = tid; i < PP; i += NT) psid[i] = g_sids[i];
    __syncthreads();

    // ---- Phase 2: Z slice -----------------------------------------------
    {
        const int ao = tid >> 2;         // 0..95
        const int cs = tid & 3;          // c-split 0..3 (64 ch each)
        const int a  = ao >> 5;          // 0..2
        const int o  = ao & 31;          // 0..31
        const int og = oq * 32 + o;      // global out channel

        const float4* wrow = reinterpret_cast<const float4*>(W)
                           + ((size_t)a * COUT + og) * (CIN / 4) + cs * 16;

        unsigned long long acc[LL];
#pragma unroll
        for (int l = 0; l < LL; l++) acc[l] = 0ull;

#pragma unroll 4
        for (int c4 = 0; c4 < 16; c4++) {
            float4 wv = wrow[c4];
            unsigned long long w01, w23;
            asm("mov.b64 %0, {%1, %2};" : "=l"(w01) : "f"(wv.x), "f"(wv.y));
            asm("mov.b64 %0, {%1, %2};" : "=l"(w23) : "f"(wv.z), "f"(wv.w));
#pragma unroll
            for (int l = 0; l < LL; l++) {
                float4 xv = xs4[l * 64 + cs * 16 + c4];
                unsigned long long x01, x23;
                asm("mov.b64 %0, {%1, %2};" : "=l"(x01) : "f"(xv.x), "f"(xv.y));
                asm("mov.b64 %0, {%1, %2};" : "=l"(x23) : "f"(xv.z), "f"(xv.w));
                ffma2(acc[l], w01, x01);
                ffma2(acc[l], w23, x23);
            }
        }
#pragma unroll
        for (int l = 0; l < LL; l++) {
            float2 f = *reinterpret_cast<float2*>(&acc[l]);
            float s = f.x + f.y;
            s += __shfl_xor_sync(0xffffffffu, s, 1);
            s += __shfl_xor_sync(0xffffffffu, s, 2);
            if (cs == 0) Zs[(l * KK + a) * 32 + o] = s;
        }
    }
    __syncthreads();

    // ---- Phase 3: build T (252 rows x 8 float4), colex unranking --------
    for (int i = tid; i < KK * NSUB * OCH; i += NT) {
        int row = i >> 3, o4 = i & 7;
        int a   = row / NSUB;
        int r   = row - a * NSUB;        // subset rank 0..83
        int l3 = 2;
#pragma unroll
        for (int t = 3; t <= 8; t++)
            if (t * (t - 1) * (t - 2) / 6 <= r) l3 = t;
        r -= l3 * (l3 - 1) * (l3 - 2) / 6;
        int l2 = 1;
#pragma unroll
        for (int t = 2; t <= 7; t++)
            if (t * (t - 1) / 2 <= r) l2 = t;
        r -= l2 * (l2 - 1) / 2;
        int l1 = r;
        float4 v1 = Zs4[(l1 * KK + a) * OCH + o4];
        float4 v2 = Zs4[(l2 * KK + a) * OCH + o4];
        float4 v3 = Zs4[(l3 * KK + a) * OCH + o4];
        float4 s;
        s.x = v1.x + v2.x + v3.x;
        s.y = v1.y + v2.y + v3.y;
        s.z = v1.z + v2.z + v3.z;
        s.w = v1.w + v2.w + v3.w;
        Tt[i] = s;
    }
    __syncthreads();

    // ---- Phase 4: gather + streaming stores -----------------------------
    // 12 warps; each warp-iter covers 4 permutations (8 lanes x 128 B each).
    const int lane = tid & 31, wid = tid >> 5;
    const int psub = lane >> 3;          // which of 4 perms
    const int o4   = lane & 7;           // float4 within 32-ch slice
    float4* outb = out + (size_t)b * PP * 64 + oq * OCH;
    for (int i = wid; i < PP / 4; i += NT / 32) {
        int p  = 4 * i + psub;
        int sp = psid[p];
        int s0 =  sp        & 1023;
        int s1 = (sp >> 10) & 1023;
        int s2 =  sp >> 20;
        float4 a0 = Tt[s0 * OCH + o4];
        float4 a1 = Tt[(NSUB + s1) * OCH + o4];
        float4 a2 = Tt[(2 * NSUB + s2) * OCH + o4];
        float4 rv;
        rv.x = a0.x + a1.x + a2.x;
        rv.y = a0.y + a1.y + a2.y;
        rv.z = a0.z + a1.z + a2.z;
        rv.w = a0.w + a1.w + a2.w;
        __stcs(&outb[(size_t)p * 64 + o4], rv);   // write-once: stream past L2
    }
}

// ---------------------------------------------------------------------------
extern "C" void kernel_launch(void* const* d_in, const int* in_sizes, int n_in,
                              void* d_out, int out_size) {
    (void)in_sizes; (void)n_in; (void)out_size;
    const float* x = (const float*)d_in[0];
    const float* W = (const float*)d_in[1];
    const float* M = (const float*)d_in[2];
    float4* y = (float4*)d_out;

    cudaFuncSetAttribute(y_fused, cudaFuncAttributeMaxDynamicSharedMemorySize, SM_ALL);

    sid_kernel<<<(PP + 255) / 256, 256>>>(M);
    dim3 grid(BB, NOQ);
    y_fused<<<grid, NT, SM_ALL>>>(x, W, y);
}